// round 9
// baseline (speedup 1.0000x reference)
#include <cuda_runtime.h>
#include <cstdint>

#define DIM    256
#define NQ     8
#define FFN    2048
#define EMBED  512
#define BS     32768                    // B * S
#define TOTAL_F4 (BS * EMBED / 4)       // 4,194,304 float4
#define GRID   1184                     // 148 SMs x 8 CTAs -> all co-resident
#define CCTAS  64                       // compute CTAs (8 warps -> 8 e's each)

// Scratch / sync (device globals — allocation-free per harness rules)
__device__ float g_o[EMBED];
__device__ int   g_flag = 0;   // compute-done arrivals (0..64)
__device__ int   g_done = 0;   // exit arrivals (for reset)

__global__ void __launch_bounds__(256, 8)   // cap regs at 32 -> 8 CTAs/SM
k_all(const float* __restrict__ U_re,
      const float* __restrict__ U_im,
      const float* __restrict__ W1,
      const float* __restrict__ b1,
      const float* __restrict__ W2,
      const float* __restrict__ b2,
      float4* __restrict__ out)
{
    __shared__ float  sp[DIM];          // probabilities
    __shared__ float  sz[NQ];           // z vector
    __shared__ float4 sh4[FFN / 4];     // h (compute); [0..127] reused as row buf

    const int t    = threadIdx.x;       // 0..255
    const int lane = t & 31;
    const int warp = t >> 5;            // 0..7
    const int bid  = blockIdx.x;

    // ================= compute phase: CTAs 0..63 =================
    if (bid < CCTAS) {
        // p_t = |U[t,0]|^2  (row stride DIM)
        {
            const float re = __ldg(&U_re[t * DIM]);
            const float im = __ldg(&U_im[t * DIM]);
            sp[t] = re * re + im * im;
        }
        __syncthreads();

        // warp q reduces qubit q: sign flips on bit (7-q) of state index s
        {
            const int bit = (NQ - 1) - warp;
            float v = 0.f;
            #pragma unroll
            for (int j = 0; j < 8; ++j) {
                const int s = lane + 32 * j;
                const float pv = sp[s];
                v += ((s >> bit) & 1) ? -pv : pv;
            }
            #pragma unroll
            for (int off = 16; off > 0; off >>= 1)
                v += __shfl_xor_sync(0xFFFFFFFFu, v, off);
            if (lane == 0) sz[warp] = v;
        }
        __syncthreads();

        const float z0 = sz[0], z1 = sz[1], z2 = sz[2], z3 = sz[3];
        const float z4 = sz[4], z5 = sz[5], z6 = sz[6], z7 = sz[7];

        // h rows t*8 .. t*8+7, one row per iteration (low register footprint)
        {
            float* sh = (float*)sh4;
            const float4* __restrict__ w1v = (const float4*)(W1 + t * 8 * NQ);
            #pragma unroll
            for (int k = 0; k < 8; ++k) {
                const float4 a = __ldg(&w1v[k * 2]);
                const float4 b = __ldg(&w1v[k * 2 + 1]);
                float acc = __ldg(&b1[t * 8 + k]);
                acc += z0*a.x + z1*a.y + z2*a.z + z3*a.w;
                acc += z4*b.x + z5*b.y + z6*b.z + z7*b.w;
                sh[t * 8 + k] = fmaxf(acc, 0.f);
            }
        }
        __syncthreads();

        // o[e]: warp w -> e = bid*8 + w
        const int e = bid * 8 + warp;
        const float4* __restrict__ w2v = (const float4*)(W2 + (size_t)e * FFN);
        float acc = 0.f;
        #pragma unroll 4
        for (int i = lane; i < FFN / 4; i += 32) {
            const float4 w = __ldg(&w2v[i]);
            const float4 h = sh4[i];
            acc += w.x*h.x + w.y*h.y + w.z*h.z + w.w*h.w;
        }
        #pragma unroll
        for (int off = 16; off > 0; off >>= 1)
            acc += __shfl_xor_sync(0xFFFFFFFFu, acc, off);

        if (lane == 0) {
            g_o[e] = acc + __ldg(&b2[e]);
            __threadfence();            // per-writer: order g_o before arrival
        }
        __syncthreads();
        if (t == 0) atomicAdd(&g_flag, 1);   // single RMW per compute CTA
    }

    // ===== handoff: volatile polling (no RMW), nanosleep backoff =====
    if (t == 0) {
        volatile int* vf = &g_flag;
        while (*vf < CCTAS)
            __nanosleep(64);
    }
    __syncthreads();

    // ================= broadcast phase: all CTAs =================
    if (t < EMBED / 4) {
        const float* go = (const float*)g_o;
        float4 v;
        v.x = __ldcg(go + t * 4 + 0);   // L2-coherent reads
        v.y = __ldcg(go + t * 4 + 1);
        v.z = __ldcg(go + t * 4 + 2);
        v.w = __ldcg(go + t * 4 + 3);
        sh4[t] = v;
    }
    __syncthreads();

    unsigned idx = bid * 256u + t;
    const unsigned stride = GRID * 256u;            // multiple of 128
    const float4 v = sh4[idx & (EMBED / 4 - 1)];    // column loop-invariant

    for (; idx < TOTAL_F4; idx += stride)
        out[idx] = v;

    // ================= reset for next graph replay =================
    __syncthreads();
    if (t == 0) {
        if (atomicAdd(&g_done, 1) == GRID - 1) {    // last CTA out resets
            g_flag = 0;
            g_done = 0;
            __threadfence();
        }
    }
}

// ---------------------------------------------------------------------------
extern "C" void kernel_launch(void* const* d_in, const int* in_sizes, int n_in,
                              void* d_out, int out_size)
{
    // metadata order: x, U_re, U_im, W1, b1, W2, b2  (x unused by the math)
    const float* U_re = (const float*)d_in[1];
    const float* U_im = (const float*)d_in[2];
    const float* W1   = (const float*)d_in[3];
    const float* b1   = (const float*)d_in[4];
    const float* W2   = (const float*)d_in[5];
    const float* b2   = (const float*)d_in[6];
    float*       out  = (float*)d_out;

    k_all<<<GRID, 256>>>(U_re, U_im, W1, b1, W2, b2, (float4*)out);
}

// round 10
// speedup vs baseline: 1.1719x; 1.1719x over previous
#include <cuda_runtime.h>
#include <cstdint>

#define DIM    256
#define NQ     8
#define FFN    2048
#define EMBED  512
#define BS     32768                    // B * S
#define TOTAL_F4 (BS * EMBED / 4)       // 4,194,304 float4
#define BCAST_CTAS 1184                 // 148 SMs x 8 (measured-best config)

// Scratch (device global — allocation-free per harness rules)
__device__ float g_o[EMBED];

// ---------------------------------------------------------------------------
// Kernel A: z -> h -> o.  64 CTAs x 256 threads; CTA b owns e = b*8..b*8+7.
// W1/b1 loads are issued BEFORE the z reduction so their memory latency
// overlaps the reduction instead of serializing after it.
// ---------------------------------------------------------------------------
__global__ void k_fused_h_o(const float* __restrict__ U_re,
                            const float* __restrict__ U_im,
                            const float* __restrict__ W1,
                            const float* __restrict__ b1,
                            const float* __restrict__ W2,
                            const float* __restrict__ b2)
{
    __shared__ float  sp[DIM];         // probabilities
    __shared__ float  sz[NQ];          // z vector
    __shared__ float4 sh4[FFN / 4];    // full h, 8 KB

    const int t    = threadIdx.x;      // 0..255
    const int lane = t & 31;
    const int warp = t >> 5;           // 0..7

    // ---- issue ALL independent loads up front (U column + W1 rows + b1) ----
    const float re = __ldg(&U_re[t * DIM]);      // row stride DIM
    const float im = __ldg(&U_im[t * DIM]);

    const float4* __restrict__ w1v = (const float4*)(W1 + t * 8 * NQ);
    float4 w1r[16];                     // 8 rows x 8 coeffs = 16 float4
    #pragma unroll
    for (int i = 0; i < 16; ++i) w1r[i] = __ldg(&w1v[i]);
    const float4 bb0 = __ldg((const float4*)(b1 + t * 8));
    const float4 bb1 = __ldg((const float4*)(b1 + t * 8 + 4));

    // ---- probabilities + z reduction (overlaps the loads above) ----
    sp[t] = re * re + im * im;
    __syncthreads();

    {   // warp q reduces qubit q: sign flips on bit (7-q) of state index s
        const int bit = (NQ - 1) - warp;
        float v = 0.f;
        #pragma unroll
        for (int j = 0; j < 8; ++j) {
            const int s = lane + 32 * j;
            const float pv = sp[s];
            v += ((s >> bit) & 1) ? -pv : pv;
        }
        #pragma unroll
        for (int off = 16; off > 0; off >>= 1)
            v += __shfl_xor_sync(0xFFFFFFFFu, v, off);
        if (lane == 0) sz[warp] = v;
    }
    __syncthreads();

    const float z0 = sz[0], z1 = sz[1], z2 = sz[2], z3 = sz[3];
    const float z4 = sz[4], z5 = sz[5], z6 = sz[6], z7 = sz[7];

    // ---- h rows t*8 .. t*8+7 from the prefetched registers ----
    {
        const float bias[8] = { bb0.x, bb0.y, bb0.z, bb0.w,
                                bb1.x, bb1.y, bb1.z, bb1.w };
        float hv[8];
        #pragma unroll
        for (int k = 0; k < 8; ++k) {
            const float4 a = w1r[k * 2];
            const float4 b = w1r[k * 2 + 1];
            float acc = bias[k];
            acc += z0*a.x + z1*a.y + z2*a.z + z3*a.w;
            acc += z4*b.x + z5*b.y + z6*b.z + z7*b.w;
            hv[k] = fmaxf(acc, 0.f);
        }
        sh4[t * 2]     = make_float4(hv[0], hv[1], hv[2], hv[3]);
        sh4[t * 2 + 1] = make_float4(hv[4], hv[5], hv[6], hv[7]);
    }
    __syncthreads();

    // ---- o[e]: warp w -> e = blockIdx*8 + w ----
    const int e = blockIdx.x * 8 + warp;
    const float4* __restrict__ w2v = (const float4*)(W2 + (size_t)e * FFN);

    float acc = 0.f;
    #pragma unroll 8
    for (int i = lane; i < FFN / 4; i += 32) {
        const float4 w = __ldg(&w2v[i]);
        const float4 h = sh4[i];
        acc += w.x*h.x + w.y*h.y + w.z*h.z + w.w*h.w;
    }
    #pragma unroll
    for (int off = 16; off > 0; off >>= 1)
        acc += __shfl_xor_sync(0xFFFFFFFFu, acc, off);

    if (lane == 0) g_o[e] = acc + __ldg(&b2[e]);
}

// ---------------------------------------------------------------------------
// Kernel B: broadcast o[512] into out — exact measured-best config (12.83us):
// 1184 CTAs x 256 threads, hoisted row value, grid-stride STG.128.
// ---------------------------------------------------------------------------
__global__ void k_broadcast(float4* __restrict__ out)
{
    __shared__ float4 so[EMBED / 4];
    if (threadIdx.x < EMBED / 4)
        so[threadIdx.x] = ((const float4*)g_o)[threadIdx.x];
    __syncthreads();

    unsigned idx    = blockIdx.x * blockDim.x + threadIdx.x;
    const unsigned stride = BCAST_CTAS * 256u;    // multiple of 128
    const float4 v = so[idx & (EMBED / 4 - 1)];   // column loop-invariant

    for (; idx < TOTAL_F4; idx += stride)
        out[idx] = v;
}

// ---------------------------------------------------------------------------
extern "C" void kernel_launch(void* const* d_in, const int* in_sizes, int n_in,
                              void* d_out, int out_size)
{
    // metadata order: x, U_re, U_im, W1, b1, W2, b2  (x unused by the math)
    const float* U_re = (const float*)d_in[1];
    const float* U_im = (const float*)d_in[2];
    const float* W1   = (const float*)d_in[3];
    const float* b1   = (const float*)d_in[4];
    const float* W2   = (const float*)d_in[5];
    const float* b2   = (const float*)d_in[6];
    float*       out  = (float*)d_out;

    k_fused_h_o<<<EMBED / 8, 256>>>(U_re, U_im, W1, b1, W2, b2);
    k_broadcast<<<BCAST_CTAS, 256>>>((float4*)out);
}

// round 11
// speedup vs baseline: 1.2950x; 1.1050x over previous
#include <cuda_runtime.h>
#include <cstdint>

#define DIM    256
#define NQ     8
#define FFN    2048
#define EMBED  512
#define BS     32768                    // B * S
#define TOTAL_F4 (BS * EMBED / 4)       // 4,194,304 float4
#define BCAST_CTAS 1184                 // 148 SMs x 8 (measured-best config)

// Scratch (device global — allocation-free per harness rules)
__device__ float g_o[EMBED];

// ---------------------------------------------------------------------------
// Kernel A (exact R4/R7 body — the two 18.9us runs): z -> h -> o.
// 64 CTAs x 256 threads; CTA b owns e = b*8 .. b*8+7.
// ---------------------------------------------------------------------------
__global__ void k_fused_h_o(const float* __restrict__ U_re,
                            const float* __restrict__ U_im,
                            const float* __restrict__ W1,
                            const float* __restrict__ b1,
                            const float* __restrict__ W2,
                            const float* __restrict__ b2)
{
    __shared__ float  sp[DIM];         // probabilities
    __shared__ float  sz[NQ];          // z vector
    __shared__ float4 sh4[FFN / 4];    // full h, 8 KB

    const int t    = threadIdx.x;      // 0..255
    const int lane = t & 31;
    const int warp = t >> 5;           // 0..7

    // p_t = |U[t,0]|^2  (row stride DIM)
    {
        const float re = __ldg(&U_re[t * DIM]);
        const float im = __ldg(&U_im[t * DIM]);
        sp[t] = re * re + im * im;
    }
    __syncthreads();

    // warp q reduces qubit q: sign flips on bit (7-q) of state index s
    {
        const int bit = (NQ - 1) - warp;
        float v = 0.f;
        #pragma unroll
        for (int j = 0; j < 8; ++j) {
            const int s = lane + 32 * j;
            const float pv = sp[s];
            v += ((s >> bit) & 1) ? -pv : pv;
        }
        #pragma unroll
        for (int off = 16; off > 0; off >>= 1)
            v += __shfl_xor_sync(0xFFFFFFFFu, v, off);
        if (lane == 0) sz[warp] = v;
    }
    __syncthreads();

    const float z0 = sz[0], z1 = sz[1], z2 = sz[2], z3 = sz[3];
    const float z4 = sz[4], z5 = sz[5], z6 = sz[6], z7 = sz[7];

    // h rows t*8 .. t*8+7   (W1 is (FFN, 8) row-major)
    {
        const float4* __restrict__ w1v = (const float4*)(W1 + t * 8 * NQ);
        const float4 bb0 = __ldg((const float4*)(b1 + t * 8));
        const float4 bb1 = __ldg((const float4*)(b1 + t * 8 + 4));
        const float bias[8] = { bb0.x, bb0.y, bb0.z, bb0.w,
                                bb1.x, bb1.y, bb1.z, bb1.w };
        float hv[8];
        #pragma unroll
        for (int k = 0; k < 8; ++k) {
            const float4 a = __ldg(&w1v[k * 2]);
            const float4 b = __ldg(&w1v[k * 2 + 1]);
            float acc = bias[k];
            acc += z0*a.x + z1*a.y + z2*a.z + z3*a.w;
            acc += z4*b.x + z5*b.y + z6*b.z + z7*b.w;
            hv[k] = fmaxf(acc, 0.f);
        }
        sh4[t * 2]     = make_float4(hv[0], hv[1], hv[2], hv[3]);
        sh4[t * 2 + 1] = make_float4(hv[4], hv[5], hv[6], hv[7]);
    }
    __syncthreads();

    // o[e]: warp w -> e = blockIdx*8 + w
    const int e = blockIdx.x * 8 + warp;
    const float4* __restrict__ w2v = (const float4*)(W2 + (size_t)e * FFN);

    float acc = 0.f;
    #pragma unroll
    for (int i = lane; i < FFN / 4; i += 32) {
        const float4 w = __ldg(&w2v[i]);
        const float4 h = sh4[i];
        acc += w.x*h.x + w.y*h.y + w.z*h.z + w.w*h.w;
    }
    #pragma unroll
    for (int off = 16; off > 0; off >>= 1)
        acc += __shfl_xor_sync(0xFFFFFFFFu, acc, off);

    if (lane == 0) g_o[e] = acc + __ldg(&b2[e]);
}

// ---------------------------------------------------------------------------
// Kernel B: broadcast with STREAMING stores (st.global.cs, evict-first).
// Output is write-once/never-re-read -> don't let L2 retain dirty lines;
// engage the DRAM write-streaming path instead of the L2-allocate wall.
// ---------------------------------------------------------------------------
__global__ void __launch_bounds__(256)
k_broadcast(float4* __restrict__ out)
{
    __shared__ float4 so[EMBED / 4];
    if (threadIdx.x < EMBED / 4)
        so[threadIdx.x] = ((const float4*)g_o)[threadIdx.x];
    __syncthreads();

    unsigned idx    = blockIdx.x * blockDim.x + threadIdx.x;
    const unsigned stride = BCAST_CTAS * 256u;    // multiple of 128
    const float4 v = so[idx & (EMBED / 4 - 1)];   // column loop-invariant

    for (; idx < TOTAL_F4; idx += stride)
        __stcs(out + idx, v);                     // st.global.cs.v4.f32
}

// ---------------------------------------------------------------------------
extern "C" void kernel_launch(void* const* d_in, const int* in_sizes, int n_in,
                              void* d_out, int out_size)
{
    // metadata order: x, U_re, U_im, W1, b1, W2, b2  (x unused by the math)
    const float* U_re = (const float*)d_in[1];
    const float* U_im = (const float*)d_in[2];
    const float* W1   = (const float*)d_in[3];
    const float* b1   = (const float*)d_in[4];
    const float* W2   = (const float*)d_in[5];
    const float* b2   = (const float*)d_in[6];
    float*       out  = (float*)d_out;

    k_fused_h_o<<<EMBED / 8, 256>>>(U_re, U_im, W1, b1, W2, b2);
    k_broadcast<<<BCAST_CTAS, 256>>>((float4*)out);
}

// round 12
// speedup vs baseline: 1.3147x; 1.0152x over previous
#include <cuda_runtime.h>
#include <cstdint>

#define DIM    256
#define NQ     8
#define FFN    2048
#define EMBED  512
#define BS     32768                    // B * S
#define TOTAL_F4 (BS * EMBED / 4)       // 4,194,304 float4
#define BCTAS  1024                     // 1024*256*16 == TOTAL_F4 exactly
#define UNROLL 16

// Scratch (device global — allocation-free per harness rules)
__device__ float g_o[EMBED];

// ---------------------------------------------------------------------------
// Kernel A (exact R4/R7 body — best measured): z -> h -> o.
// 64 CTAs x 256 threads; CTA b owns e = b*8 .. b*8+7.
// ---------------------------------------------------------------------------
__global__ void k_fused_h_o(const float* __restrict__ U_re,
                            const float* __restrict__ U_im,
                            const float* __restrict__ W1,
                            const float* __restrict__ b1,
                            const float* __restrict__ W2,
                            const float* __restrict__ b2)
{
    __shared__ float  sp[DIM];         // probabilities
    __shared__ float  sz[NQ];          // z vector
    __shared__ float4 sh4[FFN / 4];    // full h, 8 KB

    const int t    = threadIdx.x;      // 0..255
    const int lane = t & 31;
    const int warp = t >> 5;           // 0..7

    // p_t = |U[t,0]|^2  (row stride DIM)
    {
        const float re = __ldg(&U_re[t * DIM]);
        const float im = __ldg(&U_im[t * DIM]);
        sp[t] = re * re + im * im;
    }
    __syncthreads();

    // warp q reduces qubit q: sign flips on bit (7-q) of state index s
    {
        const int bit = (NQ - 1) - warp;
        float v = 0.f;
        #pragma unroll
        for (int j = 0; j < 8; ++j) {
            const int s = lane + 32 * j;
            const float pv = sp[s];
            v += ((s >> bit) & 1) ? -pv : pv;
        }
        #pragma unroll
        for (int off = 16; off > 0; off >>= 1)
            v += __shfl_xor_sync(0xFFFFFFFFu, v, off);
        if (lane == 0) sz[warp] = v;
    }
    __syncthreads();

    const float z0 = sz[0], z1 = sz[1], z2 = sz[2], z3 = sz[3];
    const float z4 = sz[4], z5 = sz[5], z6 = sz[6], z7 = sz[7];

    // h rows t*8 .. t*8+7   (W1 is (FFN, 8) row-major)
    {
        const float4* __restrict__ w1v = (const float4*)(W1 + t * 8 * NQ);
        const float4 bb0 = __ldg((const float4*)(b1 + t * 8));
        const float4 bb1 = __ldg((const float4*)(b1 + t * 8 + 4));
        const float bias[8] = { bb0.x, bb0.y, bb0.z, bb0.w,
                                bb1.x, bb1.y, bb1.z, bb1.w };
        float hv[8];
        #pragma unroll
        for (int k = 0; k < 8; ++k) {
            const float4 a = __ldg(&w1v[k * 2]);
            const float4 b = __ldg(&w1v[k * 2 + 1]);
            float acc = bias[k];
            acc += z0*a.x + z1*a.y + z2*a.z + z3*a.w;
            acc += z4*b.x + z5*b.y + z6*b.z + z7*b.w;
            hv[k] = fmaxf(acc, 0.f);
        }
        sh4[t * 2]     = make_float4(hv[0], hv[1], hv[2], hv[3]);
        sh4[t * 2 + 1] = make_float4(hv[4], hv[5], hv[6], hv[7]);
    }
    __syncthreads();

    // o[e]: warp w -> e = blockIdx*8 + w
    const int e = blockIdx.x * 8 + warp;
    const float4* __restrict__ w2v = (const float4*)(W2 + (size_t)e * FFN);

    float acc = 0.f;
    #pragma unroll
    for (int i = lane; i < FFN / 4; i += 32) {
        const float4 w = __ldg(&w2v[i]);
        const float4 h = sh4[i];
        acc += w.x*h.x + w.y*h.y + w.z*h.z + w.w*h.w;
    }
    #pragma unroll
    for (int off = 16; off > 0; off >>= 1)
        acc += __shfl_xor_sync(0xFFFFFFFFu, acc, off);

    if (lane == 0) g_o[e] = acc + __ldg(&b2[e]);
}

// ---------------------------------------------------------------------------
// Kernel B: broadcast — 1024 CTAs x 256 thr x exactly 16 unrolled STG.128.
// Exact cover of the output: no loop bounds, no tail, maximal store batching.
// ---------------------------------------------------------------------------
__global__ void __launch_bounds__(256)
k_broadcast(float4* __restrict__ out)
{
    __shared__ float4 so[EMBED / 4];
    if (threadIdx.x < EMBED / 4)
        so[threadIdx.x] = ((const float4*)g_o)[threadIdx.x];
    __syncthreads();

    const unsigned idx0 = blockIdx.x * 256u + threadIdx.x;
    const float4 v = so[idx0 & (EMBED / 4 - 1)];   // column loop-invariant

    float4* __restrict__ p = out + idx0;
    #pragma unroll
    for (int k = 0; k < UNROLL; ++k)
        p[(size_t)k * (BCTAS * 256u)] = v;
}

// ---------------------------------------------------------------------------
extern "C" void kernel_launch(void* const* d_in, const int* in_sizes, int n_in,
                              void* d_out, int out_size)
{
    // metadata order: x, U_re, U_im, W1, b1, W2, b2  (x unused by the math)
    const float* U_re = (const float*)d_in[1];
    const float* U_im = (const float*)d_in[2];
    const float* W1   = (const float*)d_in[3];
    const float* b1   = (const float*)d_in[4];
    const float* W2   = (const float*)d_in[5];
    const float* b2   = (const float*)d_in[6];
    float*       out  = (float*)d_out;

    k_fused_h_o<<<EMBED / 8, 256>>>(U_re, U_im, W1, b1, W2, b2);
    k_broadcast<<<BCTAS, 256>>>((float4*)out);
}